// round 16
// baseline (speedup 1.0000x reference)
#include <cuda_runtime.h>

// Spline2D monolithic. out[b,i,j] = sum_{u,v} bx[u]*by[v]*coeffs[u+2+r, v+2+c],
//   r = i-(floor(x)+96), c = j-(floor(y)+96), valid r,c in [0,64]; else 0.
//
// One block (256 thr, 8 CTA/SM -> grid of 1024 is a SINGLE WAVE) per batch:
//   Phase A: zero-fill all non-window float4 quads FIRST (default cache policy —
//            L2 buffers the dirty stream; drain pipelines across graph replays).
//   Phase B: rowblend rb[r][cc] = sum_u bx[u]*coeffs[r+2+u][cc+2] (65x68 smem).
//   Phase C: window quads: column-blend from rb on the fly, masked edges.

#define OH 256
#define OW 256
#define CO 72      // coeffs leading dim

__device__ __forceinline__ void bspline3(float p, float& b0, float& b1, float& b2, float& b3) {
    const float p2 = p * p, p3 = p2 * p, q = 1.0f - p;
    b0 = p3 * (1.0f / 6.0f);
    b1 = -0.5f * p3 + 0.5f * p2 + 0.5f * p + (1.0f / 6.0f);
    b2 =  0.5f * p3 - p2 + (2.0f / 3.0f);
    b3 = q * q * q * (1.0f / 6.0f);
}

__global__ __launch_bounds__(256, 8) void spline2d_kernel(
    const float* __restrict__ coeffs,
    const float* __restrict__ xv,
    const float* __restrict__ yv,
    float* __restrict__ out)
{
    __shared__ float rb[65 * 68];   // rowblend, stride 68 (17.7 KB)

    const int b = blockIdx.x;
    const float x = xv[b], y = yv[b];
    const float fx = floorf(x), fy = floorf(y);
    const int rbase = (int)fx + 96;          // window top row in output
    const int cbase = (int)fy + 96;          // window left col in output
    const float sx = x - fx, sy = y - fy;

    float bx0, bx1, bx2, bx3, by0, by1, by2, by3;
    bspline3(sx, bx0, bx1, bx2, bx3);
    bspline3(sy, by0, by1, by2, by3);

    const int t = threadIdx.x;
    float4* outp = (float4*)(out + (size_t)b * (OH * OW));

    // ---- Phase A: zero stores first (default policy, no deps) -------------
    // quad q: row i = q>>6, cols j0..j0+3, j0 = (q&63)<<2.
    // window-overlapping iff (i-rbase) in [0,64] AND (j0-cbase) in [-3,64].
    {
        const float4 z = make_float4(0.f, 0.f, 0.f, 0.f);
        #pragma unroll
        for (int k = 0; k < 16; k++) {
            const int q  = t + k * 256;
            const int r  = (q >> 6) - rbase;
            const int c  = ((q & 63) << 2) - cbase;
            if (!(((unsigned)r <= 64u) & (c >= -3) & (c <= 64)))
                outp[q] = z;
        }
    }

    // ---- Phase B: rowblend into smem (65*68 = 4420 items) -----------------
    #pragma unroll 4
    for (int idx = t; idx < 65 * 68; idx += 256) {
        const int r  = idx / 68;
        const int cc = idx - r * 68;
        const float* cp = coeffs + (r + 2) * CO + (cc + 2);
        rb[idx] = bx0 * cp[0] + bx1 * cp[CO] + bx2 * cp[2 * CO] + bx3 * cp[3 * CO];
    }
    __syncthreads();

    // ---- Phase C: window quads (col-blend on the fly) ----------------------
    // quad col index f: j0 = 4f in [cbase-3, cbase+64] ∩ [0,252].
    int f_lo = cbase - 3;  if (f_lo < 0)   f_lo = 0;
    int f_hi = cbase + 64; if (f_hi > 252) f_hi = 252;
    const int f_start = (f_lo + 3) >> 2;
    const int f_end   = f_hi >> 2;
    const int nf      = f_end - f_start + 1;

    if (nf > 0) {
        const int total = 65 * nf;
        for (int idx = t; idx < total; idx += 256) {
            const int r  = idx / nf;
            const int fi = idx - r * nf;
            const int i  = rbase + r;
            if ((unsigned)i < 256u) {
                const int f = f_start + fi;
                const int c = (f << 2) - cbase;            // template col of elem 0
                const float* rp = rb + r * 68;
                float4 v;
                float* vl = (float*)&v;
                #pragma unroll
                for (int m = 0; m < 4; m++) {
                    const int cm = c + m;
                    vl[m] = ((unsigned)cm <= 64u)
                          ? by0 * rp[cm] + by1 * rp[cm + 1] + by2 * rp[cm + 2] + by3 * rp[cm + 3]
                          : 0.0f;
                }
                outp[i * 64 + f] = v;
            }
        }
    }
}

extern "C" void kernel_launch(void* const* d_in, const int* in_sizes, int n_in,
                              void* d_out, int out_size) {
    const float* coeffs = (const float*)d_in[0];   // (72,72) f32
    const float* x      = (const float*)d_in[1];   // (1024,1,1,1) f32
    const float* y      = (const float*)d_in[2];   // (1024,1,1,1) f32
    float* out          = (float*)d_out;           // (1024,1,256,256) f32

    const int batch = in_sizes[1];                 // 1024
    spline2d_kernel<<<batch, 256>>>(coeffs, x, y, out);
}

// round 17
// speedup vs baseline: 1.0817x; 1.0817x over previous
#include <cuda_runtime.h>

// Spline2D monolithic. out[b,i,j] = sum_{u,v} bx[u]*by[v]*coeffs[u+2+r, v+2+c],
//   r = i-(floor(x)+96), c = j-(floor(y)+96), valid r,c in [0,64]; else 0.
//
// One block (512 thr, 4 CTA/SM -> 1.73 waves) per batch element:
//   Phase A: zero-fill all non-window float4 quads FIRST (default cache policy —
//            L2 buffers the dirty stream; drain pipelines across graph replays).
//   Phase B: rowblend rb[r][cc] = sum_u bx[u]*coeffs[r+2+u][cc+2] (65x68 smem).
//   Phase C: window quads: column-blend from rb on the fly, masked edges.
//
// NOTE: kernel runs at ~11.4 TB/s through L2 (~LTS cap). Bytes are mandatory
// (268 MB fp32, poisoned output) — the remaining lever is wave-tail trim only.

#define OH 256
#define OW 256
#define CO 72      // coeffs leading dim

__device__ __forceinline__ void bspline3(float p, float& b0, float& b1, float& b2, float& b3) {
    const float p2 = p * p, p3 = p2 * p, q = 1.0f - p;
    b0 = p3 * (1.0f / 6.0f);
    b1 = -0.5f * p3 + 0.5f * p2 + 0.5f * p + (1.0f / 6.0f);
    b2 =  0.5f * p3 - p2 + (2.0f / 3.0f);
    b3 = q * q * q * (1.0f / 6.0f);
}

__global__ __launch_bounds__(512, 4) void spline2d_kernel(
    const float* __restrict__ coeffs,
    const float* __restrict__ xv,
    const float* __restrict__ yv,
    float* __restrict__ out)
{
    __shared__ float rb[65 * 68];   // rowblend, stride 68 (17.7 KB)

    const int b = blockIdx.x;
    const float x = xv[b], y = yv[b];
    const float fx = floorf(x), fy = floorf(y);
    const int rbase = (int)fx + 96;          // window top row in output
    const int cbase = (int)fy + 96;          // window left col in output
    const float sx = x - fx, sy = y - fy;

    float bx0, bx1, bx2, bx3, by0, by1, by2, by3;
    bspline3(sx, bx0, bx1, bx2, bx3);
    bspline3(sy, by0, by1, by2, by3);

    const int t = threadIdx.x;
    float4* outp = (float4*)(out + (size_t)b * (OH * OW));

    // ---- Phase A: zero stores first (default policy, no deps) -------------
    // quad q: row i = q>>6, cols j0..j0+3, j0 = (q&63)<<2.
    // window-overlapping iff (i-rbase) in [0,64] AND (j0-cbase) in [-3,64].
    {
        const float4 z = make_float4(0.f, 0.f, 0.f, 0.f);
        #pragma unroll
        for (int k = 0; k < 8; k++) {
            const int q  = t + k * 512;
            const int r  = (q >> 6) - rbase;
            const int c  = ((q & 63) << 2) - cbase;
            if (!(((unsigned)r <= 64u) & (c >= -3) & (c <= 64)))
                outp[q] = z;
        }
    }

    // ---- Phase B: rowblend into smem (65*68 = 4420 items) -----------------
    #pragma unroll 3
    for (int idx = t; idx < 65 * 68; idx += 512) {
        const int r  = idx / 68;
        const int cc = idx - r * 68;
        const float* cp = coeffs + (r + 2) * CO + (cc + 2);
        rb[idx] = bx0 * cp[0] + bx1 * cp[CO] + bx2 * cp[2 * CO] + bx3 * cp[3 * CO];
    }
    __syncthreads();

    // ---- Phase C: window quads (col-blend on the fly) ----------------------
    // quad col index f: j0 = 4f in [cbase-3, cbase+64] ∩ [0,252].
    int f_lo = cbase - 3;  if (f_lo < 0)   f_lo = 0;
    int f_hi = cbase + 64; if (f_hi > 252) f_hi = 252;
    const int f_start = (f_lo + 3) >> 2;
    const int f_end   = f_hi >> 2;
    const int nf      = f_end - f_start + 1;

    if (nf > 0) {
        const int total = 65 * nf;
        for (int idx = t; idx < total; idx += 512) {
            const int r  = idx / nf;
            const int fi = idx - r * nf;
            const int i  = rbase + r;
            if ((unsigned)i < 256u) {
                const int f = f_start + fi;
                const int c = (f << 2) - cbase;            // template col of elem 0
                const float* rp = rb + r * 68;
                float4 v;
                float* vl = (float*)&v;
                #pragma unroll
                for (int m = 0; m < 4; m++) {
                    const int cm = c + m;
                    vl[m] = ((unsigned)cm <= 64u)
                          ? by0 * rp[cm] + by1 * rp[cm + 1] + by2 * rp[cm + 2] + by3 * rp[cm + 3]
                          : 0.0f;
                }
                outp[i * 64 + f] = v;
            }
        }
    }
}

extern "C" void kernel_launch(void* const* d_in, const int* in_sizes, int n_in,
                              void* d_out, int out_size) {
    const float* coeffs = (const float*)d_in[0];   // (72,72) f32
    const float* x      = (const float*)d_in[1];   // (1024,1,1,1) f32
    const float* y      = (const float*)d_in[2];   // (1024,1,1,1) f32
    float* out          = (float*)d_out;           // (1024,1,256,256) f32

    const int batch = in_sizes[1];                 // 1024
    spline2d_kernel<<<batch, 512>>>(coeffs, x, y, out);
}